// round 4
// baseline (speedup 1.0000x reference)
#include <cuda_runtime.h>
#include <cuda_bf16.h>
#include <math.h>

#define HID 128
#define MAXE 800000
#define MAXN 50000

// ---- scratch (static __device__ per allocation rules) ----
__device__ float g_Y1[(size_t)MAXE * HID];     // pre-BN edge activations
__device__ float g_AGG[(size_t)MAXN * HID];    // scatter-add target
__device__ float g_H2[(size_t)MAXN * HID];     // pre-BN node activations
__device__ float g_stats1[2 * HID];
__device__ float g_stats2[2 * HID];
__device__ float g_bn1[2 * HID];
__device__ float g_bn2[2 * HID];

// split f32 into bf16 hi + bf16 lo (3-term mma gives ~2^-15 relative error)
__device__ __forceinline__ void bsplit(float v, __nv_bfloat16* hp, __nv_bfloat16* lp) {
    __nv_bfloat16 h = __float2bfloat16(v);
    *hp = h;
    *lp = __float2bfloat16(v - __bfloat162float(h));
}

__device__ __forceinline__ void mma16816(float* d, const unsigned* a, unsigned b0, unsigned b1) {
    asm volatile(
        "mma.sync.aligned.m16n8k16.row.col.f32.bf16.bf16.f32 "
        "{%0,%1,%2,%3}, {%4,%5,%6,%7}, {%8,%9}, {%0,%1,%2,%3};\n"
        : "+f"(d[0]), "+f"(d[1]), "+f"(d[2]), "+f"(d[3])
        : "r"(a[0]), "r"(a[1]), "r"(a[2]), "r"(a[3]), "r"(b0), "r"(b1));
}

// Mainloop: A[128 x K] (row-major, bf16 hi/lo), Wt[N x K] (k-contig, bf16 hi/lo).
// Warp tile 32 x (NT*8); fragments per PTX m16n8k16 layout.
template<int K, int NT>
__device__ __forceinline__ void mma_loop(
    const unsigned* __restrict__ Ah, const unsigned* __restrict__ Al,
    const unsigned* __restrict__ Wh, const unsigned* __restrict__ Wl,
    int warpM, int warpN, int g, int tig, float acc[2][NT][4])
{
    const int WP = (K + 8) / 2;   // word pitch (bf16 pitch K+8), WP % 32 == 4 -> conflict-free
#pragma unroll
    for (int kk = 0; kk < K / 16; kk++) {
        unsigned ah[2][4], al[2][4];
#pragma unroll
        for (int mt = 0; mt < 2; mt++) {
            int base = (warpM + mt * 16 + g) * WP + kk * 8 + tig;
            ah[mt][0] = Ah[base];            al[mt][0] = Al[base];
            ah[mt][1] = Ah[base + 8 * WP];   al[mt][1] = Al[base + 8 * WP];
            ah[mt][2] = Ah[base + 4];        al[mt][2] = Al[base + 4];
            ah[mt][3] = Ah[base + 8 * WP + 4]; al[mt][3] = Al[base + 8 * WP + 4];
        }
#pragma unroll
        for (int nt = 0; nt < NT; nt++) {
            int bbase = (warpN + nt * 8 + g) * WP + kk * 8 + tig;
            unsigned bh0 = Wh[bbase], bh1 = Wh[bbase + 4];
            unsigned bl0 = Wl[bbase], bl1 = Wl[bbase + 4];
#pragma unroll
            for (int mt = 0; mt < 2; mt++) {
                mma16816(acc[mt][nt], ah[mt], bh0, bh1);   // hi*hi
                mma16816(acc[mt][nt], ah[mt], bl0, bl1);   // hi*lo
                mma16816(acc[mt][nt], al[mt], bh0, bh1);   // lo*hi
            }
        }
    }
}

// stage W [K x NOUT] (row-major in gmem) -> transposed smem Wt[n][k] hi/lo
template<int K, int NOUT>
__device__ __forceinline__ void stage_W(const float* __restrict__ W,
                                        __nv_bfloat16* Wh, __nv_bfloat16* Wl, int tid) {
    const int P = K + 8;
    for (int idx = tid; idx < K * NOUT; idx += 256) {
        int k = idx / NOUT, n = idx % NOUT;
        bsplit(W[idx], &Wh[n * P + k], &Wl[n * P + k]);
    }
}

// =====================================================================
// Edge layer 1: Y1 = concat(x[row], edge_attr) @ W1a + b1a ; BN stats
// =====================================================================
__global__ __launch_bounds__(256, 1)
void k_edge_l1(const float* __restrict__ x, const int* __restrict__ row,
               const float* __restrict__ ea, const float* __restrict__ W,
               const float* __restrict__ b, int E, int nTiles)
{
    const int K = 128, NOUT = 128, NT = 8, P = K + 8;
    extern __shared__ char smraw[];
    __nv_bfloat16* Ah = (__nv_bfloat16*)smraw;
    __nv_bfloat16* Al = Ah + 128 * P;
    __nv_bfloat16* Wh = Al + 128 * P;
    __nv_bfloat16* Wl = Wh + NOUT * P;
    float* Bs   = (float*)(Wl + NOUT * P);
    float* Ssum = Bs + NOUT;
    float* Sssq = Ssum + 128;

    int tid = threadIdx.x, lane = tid & 31, wid = tid >> 5;
    int g = lane >> 2, tig = lane & 3;
    int warpM = (wid & 3) * 32, warpN = (wid >> 2) * 64;

    stage_W<K, NOUT>(W, Wh, Wl, tid);
    for (int i = tid; i < NOUT; i += 256) Bs[i] = b[i];
    if (tid < 128) { Ssum[tid] = 0.f; Sssq[tid] = 0.f; }
    __syncthreads();

    float tsum[NT][2] = {}, tssq[NT][2] = {};

    for (int tile = blockIdx.x; tile < nTiles; tile += gridDim.x) {
        int e0 = tile * 128;
        for (int idx = tid; idx < 128 * K; idx += 256) {
            int e = idx >> 7, k = idx & 127;
            int ge = e0 + e;
            float v = 0.f;
            if (ge < E) v = (k < 64) ? x[row[ge] * 64 + k] : ea[(size_t)ge * 64 + (k - 64)];
            bsplit(v, &Ah[e * P + k], &Al[e * P + k]);
        }
        __syncthreads();

        float acc[2][NT][4];
#pragma unroll
        for (int mt = 0; mt < 2; mt++)
#pragma unroll
            for (int nt = 0; nt < NT; nt++) {
                int c0 = warpN + nt * 8 + 2 * tig;
                acc[mt][nt][0] = Bs[c0]; acc[mt][nt][1] = Bs[c0 + 1];
                acc[mt][nt][2] = Bs[c0]; acc[mt][nt][3] = Bs[c0 + 1];
            }

        mma_loop<K, NT>((const unsigned*)Ah, (const unsigned*)Al,
                        (const unsigned*)Wh, (const unsigned*)Wl,
                        warpM, warpN, g, tig, acc);

#pragma unroll
        for (int mt = 0; mt < 2; mt++) {
            int r0 = e0 + warpM + mt * 16 + g, r1 = r0 + 8;
#pragma unroll
            for (int nt = 0; nt < NT; nt++) {
                int c0 = warpN + nt * 8 + 2 * tig;
                float* d = acc[mt][nt];
                if (r0 < E) {
                    *(float2*)&g_Y1[(size_t)r0 * 128 + c0] = make_float2(d[0], d[1]);
                    tsum[nt][0] += d[0]; tsum[nt][1] += d[1];
                    tssq[nt][0] += d[0] * d[0]; tssq[nt][1] += d[1] * d[1];
                }
                if (r1 < E) {
                    *(float2*)&g_Y1[(size_t)r1 * 128 + c0] = make_float2(d[2], d[3]);
                    tsum[nt][0] += d[2]; tsum[nt][1] += d[3];
                    tssq[nt][0] += d[2] * d[2]; tssq[nt][1] += d[3] * d[3];
                }
            }
        }
        __syncthreads();
    }
#pragma unroll
    for (int nt = 0; nt < NT; nt++) {
        int c = warpN + nt * 8 + 2 * tig;
        atomicAdd(&Ssum[c], tsum[nt][0]);     atomicAdd(&Ssum[c + 1], tsum[nt][1]);
        atomicAdd(&Sssq[c], tssq[nt][0]);     atomicAdd(&Sssq[c + 1], tssq[nt][1]);
    }
    __syncthreads();
    if (tid < 128) {
        atomicAdd(&g_stats1[tid], Ssum[tid]);
        atomicAdd(&g_stats1[128 + tid], Sssq[tid]);
    }
}

// =====================================================================
// BN finalize
// =====================================================================
__global__ void k_finalize(const float* __restrict__ stats,
                           const float* __restrict__ g,
                           const float* __restrict__ be,
                           float* __restrict__ bn, float invC)
{
    int j = threadIdx.x;
    float mu  = stats[j] * invC;
    float var = stats[128 + j] * invC - mu * mu;
    float sc  = g[j] * rsqrtf(var + 1e-5f);
    bn[j]       = sc;
    bn[128 + j] = be[j] - mu * sc;
}

// =====================================================================
// Edge layer 2: relu(bn(Y1)) @ W2a + b2a ; scatter-add into g_AGG[col]
// =====================================================================
__global__ __launch_bounds__(256, 1)
void k_edge_l2(const int* __restrict__ colidx, const float* __restrict__ W,
               const float* __restrict__ b, int E, int nTiles)
{
    const int K = 128, NOUT = 128, NT = 8, P = K + 8;
    extern __shared__ char smraw[];
    __nv_bfloat16* Ah = (__nv_bfloat16*)smraw;
    __nv_bfloat16* Al = Ah + 128 * P;
    __nv_bfloat16* Wh = Al + 128 * P;
    __nv_bfloat16* Wl = Wh + NOUT * P;
    float* Bs = (float*)(Wl + NOUT * P);
    float* BN = Bs + NOUT;   // 256 floats

    int tid = threadIdx.x, lane = tid & 31, wid = tid >> 5;
    int g = lane >> 2, tig = lane & 3;
    int warpM = (wid & 3) * 32, warpN = (wid >> 2) * 64;

    stage_W<K, NOUT>(W, Wh, Wl, tid);
    for (int i = tid; i < NOUT; i += 256) Bs[i] = b[i];
    BN[tid] = g_bn1[tid];
    __syncthreads();

    for (int tile = blockIdx.x; tile < nTiles; tile += gridDim.x) {
        int e0 = tile * 128;
        for (int idx = tid; idx < 128 * K; idx += 256) {
            int e = idx >> 7, k = idx & 127;
            int ge = e0 + e;
            float v = 0.f;
            if (ge < E) {
                float y = g_Y1[(size_t)ge * 128 + k];
                v = fmaxf(fmaf(y, BN[k], BN[128 + k]), 0.f);
            }
            bsplit(v, &Ah[e * P + k], &Al[e * P + k]);
        }
        __syncthreads();

        float acc[2][NT][4];
#pragma unroll
        for (int mt = 0; mt < 2; mt++)
#pragma unroll
            for (int nt = 0; nt < NT; nt++) {
                int c0 = warpN + nt * 8 + 2 * tig;
                acc[mt][nt][0] = Bs[c0]; acc[mt][nt][1] = Bs[c0 + 1];
                acc[mt][nt][2] = Bs[c0]; acc[mt][nt][3] = Bs[c0 + 1];
            }

        mma_loop<K, NT>((const unsigned*)Ah, (const unsigned*)Al,
                        (const unsigned*)Wh, (const unsigned*)Wl,
                        warpM, warpN, g, tig, acc);

#pragma unroll
        for (int mt = 0; mt < 2; mt++) {
            int r0 = e0 + warpM + mt * 16 + g, r1 = r0 + 8;
            int c_r0 = (r0 < E) ? colidx[r0] : 0;
            int c_r1 = (r1 < E) ? colidx[r1] : 0;
#pragma unroll
            for (int nt = 0; nt < NT; nt++) {
                int c0 = warpN + nt * 8 + 2 * tig;
                float* d = acc[mt][nt];
                if (r0 < E) {
                    float* dst = g_AGG + (size_t)c_r0 * 128 + c0;
                    atomicAdd(dst, d[0]); atomicAdd(dst + 1, d[1]);
                }
                if (r1 < E) {
                    float* dst = g_AGG + (size_t)c_r1 * 128 + c0;
                    atomicAdd(dst, d[2]); atomicAdd(dst + 1, d[3]);
                }
            }
        }
        __syncthreads();
    }
}

// =====================================================================
// Node layer 1: H2 = concat(x, AGG) @ W1b + b1b ; BN stats. K = 192.
// =====================================================================
__global__ __launch_bounds__(256, 1)
void k_node_l1(const float* __restrict__ x, const float* __restrict__ W,
               const float* __restrict__ b, int N, int nTiles)
{
    const int K = 192, NOUT = 128, NT = 8, P = K + 8;
    extern __shared__ char smraw[];
    __nv_bfloat16* Ah = (__nv_bfloat16*)smraw;
    __nv_bfloat16* Al = Ah + 128 * P;
    __nv_bfloat16* Wh = Al + 128 * P;
    __nv_bfloat16* Wl = Wh + NOUT * P;
    float* Bs   = (float*)(Wl + NOUT * P);
    float* Ssum = Bs + NOUT;
    float* Sssq = Ssum + 128;

    int tid = threadIdx.x, lane = tid & 31, wid = tid >> 5;
    int g = lane >> 2, tig = lane & 3;
    int warpM = (wid & 3) * 32, warpN = (wid >> 2) * 64;

    stage_W<K, NOUT>(W, Wh, Wl, tid);
    for (int i = tid; i < NOUT; i += 256) Bs[i] = b[i];
    if (tid < 128) { Ssum[tid] = 0.f; Sssq[tid] = 0.f; }
    __syncthreads();

    float tsum[NT][2] = {}, tssq[NT][2] = {};

    for (int tile = blockIdx.x; tile < nTiles; tile += gridDim.x) {
        int n0 = tile * 128;
        for (int idx = tid; idx < 128 * K; idx += 256) {
            int e = idx / K, k = idx - e * K;
            int gn = n0 + e;
            float v = 0.f;
            if (gn < N) v = (k < 64) ? x[gn * 64 + k] : g_AGG[(size_t)gn * 128 + (k - 64)];
            bsplit(v, &Ah[e * P + k], &Al[e * P + k]);
        }
        __syncthreads();

        float acc[2][NT][4];
#pragma unroll
        for (int mt = 0; mt < 2; mt++)
#pragma unroll
            for (int nt = 0; nt < NT; nt++) {
                int c0 = warpN + nt * 8 + 2 * tig;
                acc[mt][nt][0] = Bs[c0]; acc[mt][nt][1] = Bs[c0 + 1];
                acc[mt][nt][2] = Bs[c0]; acc[mt][nt][3] = Bs[c0 + 1];
            }

        mma_loop<K, NT>((const unsigned*)Ah, (const unsigned*)Al,
                        (const unsigned*)Wh, (const unsigned*)Wl,
                        warpM, warpN, g, tig, acc);

#pragma unroll
        for (int mt = 0; mt < 2; mt++) {
            int r0 = n0 + warpM + mt * 16 + g, r1 = r0 + 8;
#pragma unroll
            for (int nt = 0; nt < NT; nt++) {
                int c0 = warpN + nt * 8 + 2 * tig;
                float* d = acc[mt][nt];
                if (r0 < N) {
                    *(float2*)&g_H2[(size_t)r0 * 128 + c0] = make_float2(d[0], d[1]);
                    tsum[nt][0] += d[0]; tsum[nt][1] += d[1];
                    tssq[nt][0] += d[0] * d[0]; tssq[nt][1] += d[1] * d[1];
                }
                if (r1 < N) {
                    *(float2*)&g_H2[(size_t)r1 * 128 + c0] = make_float2(d[2], d[3]);
                    tsum[nt][0] += d[2]; tsum[nt][1] += d[3];
                    tssq[nt][0] += d[2] * d[2]; tssq[nt][1] += d[3] * d[3];
                }
            }
        }
        __syncthreads();
    }
#pragma unroll
    for (int nt = 0; nt < NT; nt++) {
        int c = warpN + nt * 8 + 2 * tig;
        atomicAdd(&Ssum[c], tsum[nt][0]);     atomicAdd(&Ssum[c + 1], tsum[nt][1]);
        atomicAdd(&Sssq[c], tssq[nt][0]);     atomicAdd(&Sssq[c + 1], tssq[nt][1]);
    }
    __syncthreads();
    if (tid < 128) {
        atomicAdd(&g_stats2[tid], Ssum[tid]);
        atomicAdd(&g_stats2[128 + tid], Sssq[tid]);
    }
}

// =====================================================================
// Node layer 2: out = relu(bn(H2)) @ W2b + b2b. NOUT = 64.
// =====================================================================
__global__ __launch_bounds__(256, 1)
void k_node_l2(float* __restrict__ out, const float* __restrict__ W,
               const float* __restrict__ b, int N, int nTiles)
{
    const int K = 128, NOUT = 64, NT = 4, P = K + 8;
    extern __shared__ char smraw[];
    __nv_bfloat16* Ah = (__nv_bfloat16*)smraw;
    __nv_bfloat16* Al = Ah + 128 * P;
    __nv_bfloat16* Wh = Al + 128 * P;
    __nv_bfloat16* Wl = Wh + NOUT * P;
    float* Bs = (float*)(Wl + NOUT * P);
    float* BN = Bs + NOUT;   // 256 floats

    int tid = threadIdx.x, lane = tid & 31, wid = tid >> 5;
    int g = lane >> 2, tig = lane & 3;
    int warpM = (wid & 3) * 32, warpN = (wid >> 2) * 32;

    stage_W<K, NOUT>(W, Wh, Wl, tid);
    for (int i = tid; i < NOUT; i += 256) Bs[i] = b[i];
    BN[tid] = g_bn2[tid];
    __syncthreads();

    for (int tile = blockIdx.x; tile < nTiles; tile += gridDim.x) {
        int n0 = tile * 128;
        for (int idx = tid; idx < 128 * K; idx += 256) {
            int e = idx >> 7, k = idx & 127;
            int gn = n0 + e;
            float v = 0.f;
            if (gn < N) {
                float y = g_H2[(size_t)gn * 128 + k];
                v = fmaxf(fmaf(y, BN[k], BN[128 + k]), 0.f);
            }
            bsplit(v, &Ah[e * P + k], &Al[e * P + k]);
        }
        __syncthreads();

        float acc[2][NT][4];
#pragma unroll
        for (int mt = 0; mt < 2; mt++)
#pragma unroll
            for (int nt = 0; nt < NT; nt++) {
                int c0 = warpN + nt * 8 + 2 * tig;
                acc[mt][nt][0] = Bs[c0]; acc[mt][nt][1] = Bs[c0 + 1];
                acc[mt][nt][2] = Bs[c0]; acc[mt][nt][3] = Bs[c0 + 1];
            }

        mma_loop<K, NT>((const unsigned*)Ah, (const unsigned*)Al,
                        (const unsigned*)Wh, (const unsigned*)Wl,
                        warpM, warpN, g, tig, acc);

#pragma unroll
        for (int mt = 0; mt < 2; mt++) {
            int r0 = n0 + warpM + mt * 16 + g, r1 = r0 + 8;
#pragma unroll
            for (int nt = 0; nt < NT; nt++) {
                int c0 = warpN + nt * 8 + 2 * tig;
                float* d = acc[mt][nt];
                if (r0 < N) *(float2*)&out[(size_t)r0 * 64 + c0] = make_float2(d[0], d[1]);
                if (r1 < N) *(float2*)&out[(size_t)r1 * 64 + c0] = make_float2(d[2], d[3]);
            }
        }
        __syncthreads();
    }
}

// =====================================================================
extern "C" void kernel_launch(void* const* d_in, const int* in_sizes, int n_in,
                              void* d_out, int out_size)
{
    const float* x    = (const float*)d_in[0];
    const int*   ei   = (const int*)d_in[1];
    const float* ea   = (const float*)d_in[2];
    const float* W1a  = (const float*)d_in[5];
    const float* b1a  = (const float*)d_in[6];
    const float* g1a  = (const float*)d_in[7];
    const float* be1a = (const float*)d_in[8];
    const float* W2a  = (const float*)d_in[9];
    const float* b2a  = (const float*)d_in[10];
    const float* W1b  = (const float*)d_in[11];
    const float* b1b  = (const float*)d_in[12];
    const float* g1b  = (const float*)d_in[13];
    const float* be1b = (const float*)d_in[14];
    const float* W2b  = (const float*)d_in[15];
    const float* b2b  = (const float*)d_in[16];

    int N = in_sizes[0] / 64;
    int E = in_sizes[1] / 2;
    const int* row = ei;
    const int* col = ei + E;

    void *pS1, *pS2, *pAGG, *pBN1, *pBN2;
    cudaGetSymbolAddress(&pS1, g_stats1);
    cudaGetSymbolAddress(&pS2, g_stats2);
    cudaGetSymbolAddress(&pAGG, g_AGG);
    cudaGetSymbolAddress(&pBN1, g_bn1);
    cudaGetSymbolAddress(&pBN2, g_bn2);

    // smem sizes (bytes)
    const int SM_E1 = (2 * 128 * 136 + 2 * 128 * 136) * 2 + (128 + 256) * 4;  // 140800
    const int SM_E2 = SM_E1;                                                  // 140800
    const int SM_N1 = (2 * 128 * 200 + 2 * 128 * 200) * 2 + (128 + 256) * 4;  // 206336
    const int SM_N2 = (2 * 128 * 136 + 2 * 64 * 136) * 2 + (64 + 256) * 4;    // 105728

    cudaFuncSetAttribute(k_edge_l1, cudaFuncAttributeMaxDynamicSharedMemorySize, SM_E1);
    cudaFuncSetAttribute(k_edge_l2, cudaFuncAttributeMaxDynamicSharedMemorySize, SM_E2);
    cudaFuncSetAttribute(k_node_l1, cudaFuncAttributeMaxDynamicSharedMemorySize, SM_N1);
    cudaFuncSetAttribute(k_node_l2, cudaFuncAttributeMaxDynamicSharedMemorySize, SM_N2);

    cudaMemsetAsync(pS1, 0, 2 * HID * sizeof(float), 0);
    cudaMemsetAsync(pS2, 0, 2 * HID * sizeof(float), 0);
    cudaMemsetAsync(pAGG, 0, (size_t)N * HID * sizeof(float), 0);

    int tilesE = (E + 127) / 128;
    int tilesN = (N + 127) / 128;

    k_edge_l1<<<148, 256, SM_E1>>>(x, row, ea, W1a, b1a, E, tilesE);
    k_finalize<<<1, 128>>>((const float*)pS1, g1a, be1a, (float*)pBN1, 1.0f / (float)E);
    k_edge_l2<<<148, 256, SM_E2>>>(col, W2a, b2a, E, tilesE);
    k_node_l1<<<148, 256, SM_N1>>>(x, W1b, b1b, N, tilesN);
    k_finalize<<<1, 128>>>((const float*)pS2, g1b, be1b, (float*)pBN2, 1.0f / (float)N);
    k_node_l2<<<148, 256, SM_N2>>>((float*)d_out, W2b, b2b, N, tilesN);
}